// round 12
// baseline (speedup 1.0000x reference)
#include <cuda_runtime.h>
#include <cuda_fp16.h>
#include <cstdint>

#define Bsz 1024
#define Tt  128
#define Dd  64
#define Hh  256
#define MB  4            // batch rows per CTA
#define NT  256
#define GRID 256         // 2 CTAs per SM

typedef unsigned long long u64;

// ------------------- device scratch -------------------
__device__ float tdhT_g[Dd * Hh];        // td_h_W^T  [k][c]
__device__ float tdxT_g[Dd * Dd];        // td_x_W^T  [k][j]
__device__ float Gh_g[Bsz * Tt * Hh];    // gamma_h   [b*T+t][256]
__device__ float alpha_g[Bsz * Tt * Dd]; // alpha     [b*T+t][64]
__device__ __half WEHrk_g[Hh * 1024];    // lstmRK fp16
__device__ __half WEHk_g[2 * Dd * 1024]; // lstmK  fp16

__device__ __forceinline__ u64 dup2(float w) {
    u64 r; asm("mov.b64 %0, {%1,%1};" : "=l"(r) : "f"(w)); return r;
}
__device__ __forceinline__ void upk2(u64 v, float& lo, float& hi) {
    asm("mov.b64 {%0,%1}, %2;" : "=f"(lo), "=f"(hi) : "l"(v));
}
__device__ __forceinline__ u64 fma2(u64 a, u64 b, u64 c) {
    u64 d; asm("fma.rn.f32x2 %0, %1, %2, %3;" : "=l"(d) : "l"(a), "l"(b), "l"(c)); return d;
}
__device__ __forceinline__ float sigf(float x) {
    return __fdividef(1.f, 1.f + __expf(-x));
}
__device__ __forceinline__ float tanhfast(float x) {
    return __fdividef(2.f, 1.f + __expf(-2.f * x)) - 1.f;
}

// ============================ precompute kernels ============================

__global__ void transpose_kernel(const float* __restrict__ tdhW,
                                 const float* __restrict__ tdxW) {
    int idx = blockIdx.x * 256 + threadIdx.x;
    if (idx < Hh * Dd) {
        int c = idx >> 6, k = idx & 63;
        tdhT_g[k * Hh + c] = tdhW[idx];
    } else if (idx < Hh * Dd + Dd * Dd) {
        int e = idx - Hh * Dd;
        int j = e >> 6, k = e & 63;
        tdxT_g[k * Dd + j] = tdxW[e];
    }
}

__global__ void pack_h_kernel(const float* __restrict__ rk,
                              const float* __restrict__ kk) {
    int idx = blockIdx.x * 256 + threadIdx.x;
    if (idx < Hh * 1024)
        WEHrk_g[idx] = __float2half(rk[idx]);
    else if (idx < Hh * 1024 + 2 * Dd * 1024) {
        int e = idx - Hh * 1024;
        WEHk_g[e] = __float2half(kk[e]);
    }
}

// gamma_h AND (gamma_x -> alpha) for 8 rows/CTA (shares delta/mask loads)
__global__ void __launch_bounds__(256) pre_ga_kernel(
    const float* __restrict__ deltas, const float* __restrict__ masks,
    const float* __restrict__ tdhB, const float* __restrict__ tdxB,
    const float* __restrict__ wcW, const float* __restrict__ wcB)
{
    __shared__ float dp[4 * Dd * 2], mp[4 * Dd * 2], gxp[4 * Dd * 2];
    const int tid = threadIdx.x;
    const int row0 = blockIdx.x * 8;
    for (int e = tid; e < 8 * Dd; e += 256) {
        int r = e >> 6, k = e & 63;
        dp[(r >> 1) * 128 + k * 2 + (r & 1)] = deltas[(row0 + r) * Dd + k];
        mp[(r >> 1) * 128 + k * 2 + (r & 1)] = masks[(row0 + r) * Dd + k];
    }
    __syncthreads();

    {
        const int c = tid;
        u64 a[4];
        #pragma unroll
        for (int p = 0; p < 4; p++) a[p] = 0ULL;
        #pragma unroll 4
        for (int k = 0; k < Dd; k++) {
            u64 wd = dup2(tdhT_g[k * Hh + c]);
            #pragma unroll
            for (int p = 0; p < 4; p++)
                a[p] = fma2(*(const u64*)(dp + p * 128 + k * 2), wd, a[p]);
        }
        float bb = tdhB[c];
        #pragma unroll
        for (int p = 0; p < 4; p++) {
            float a0, a1; upk2(a[p], a0, a1);
            Gh_g[(row0 + 2 * p)     * Hh + c] = __expf(-fmaxf(a0 + bb, 0.f));
            Gh_g[(row0 + 2 * p + 1) * Hh + c] = __expf(-fmaxf(a1 + bb, 0.f));
        }
    }

    const int j = tid & 63, pg = tid >> 6;
    u64 g = dup2(tdxB[j]);
    #pragma unroll 4
    for (int k = 0; k < Dd; k++)
        g = fma2(*(const u64*)(dp + pg * 128 + k * 2), dup2(tdxT_g[k * Dd + j]), g);
    float g0, g1; upk2(g, g0, g1);
    gxp[pg * 128 + j * 2 + 0] = __expf(-fmaxf(g0, 0.f));
    gxp[pg * 128 + j * 2 + 1] = __expf(-fmaxf(g1, 0.f));
    __syncthreads();
    u64 al = dup2(wcB[j]);
    #pragma unroll 4
    for (int k = 0; k < Dd; k++) {
        al = fma2(*(const u64*)(gxp + pg * 128 + k * 2), dup2(wcW[k * Dd + j]), al);
        al = fma2(*(const u64*)(mp  + pg * 128 + k * 2), dup2(wcW[(Dd + k) * Dd + j]), al);
    }
    float a0, a1; upk2(al, a0, a1);
    alpha_g[(row0 + 2 * pg)     * Dd + j] = a0;
    alpha_g[(row0 + 2 * pg + 1) * Dd + j] = a1;
}

// ============================ main recurrent kernel ============================
// MB=4 rows per CTA, 2 pairs. 256 threads. 2 CTAs/SM.

struct __align__(16) Smem {
    __half histh[Hh * Dd];    // 32 KB  hist_W fp16 [k][j]
    float frT[Dd * Dd];       // 16 KB
    float hp[2 * 2 * Hh];     //  4 KB  h paired [p][c*2+par], p in {0,1}
    float cs[MB * Hh];        //  4 KB
    float zp[2 * 2 * 4 * Hh]; // 16 KB  gate acts [p][col*2+par] (alias: partials)
    float gh[MB * Hh];        //  4 KB  G_h[t+1] staging [r][c]
    float xs[MB * Dd], ms[MB * Dd];
    float mp[2 * 2 * Dd];     // paired m [p][k*2+par]
    float alp[2 * 2 * Dd];
    float xcp[2 * 2 * Dd], xhp[2 * 2 * Dd], ccp[2 * 2 * Dd];
    float hist_b[Dd], fr_b[Dd];
};

// one k-pair (k0, k0+1): wk0/wk1 = uint2 of 4 fp16 cols each; 2 pairs from src
template <int STRIDE>
__device__ __forceinline__ void eblk2(const float* src, int k0,
                                      uint2 wk0, uint2 wk1, u64 (&acc)[4][2]) {
    float2 w0a = __half22float2(*reinterpret_cast<const __half2*>(&wk0.x));
    float2 w0b = __half22float2(*reinterpret_cast<const __half2*>(&wk0.y));
    float2 w1a = __half22float2(*reinterpret_cast<const __half2*>(&wk1.x));
    float2 w1b = __half22float2(*reinterpret_cast<const __half2*>(&wk1.y));
    u64 W0[4] = {dup2(w0a.x), dup2(w0a.y), dup2(w0b.x), dup2(w0b.y)};
    u64 W1[4] = {dup2(w1a.x), dup2(w1a.y), dup2(w1b.x), dup2(w1b.y)};
    #pragma unroll
    for (int p = 0; p < 2; p++) {
        float4 hv = *(const float4*)(src + p * STRIDE + k0 * 2);
        u64 h0 = ((const u64*)&hv)[0];   // k0   (par0, par1)
        u64 h1 = ((const u64*)&hv)[1];   // k0+1
        #pragma unroll
        for (int c = 0; c < 4; c++) {
            acc[c][p] = fma2(h0, W0[c], acc[c][p]);
            acc[c][p] = fma2(h1, W1[c], acc[c][p]);
        }
    }
}

__global__ void __launch_bounds__(NT, 2) rits_kernel(
    const float* __restrict__ values, const float* __restrict__ masks,
    const float* __restrict__ histW, const float* __restrict__ histB,
    const float* __restrict__ frW, const float* __restrict__ frB,
    const float* __restrict__ lstmB,
    const float* __restrict__ outW, const float* __restrict__ outB,
    float* __restrict__ yout, float* __restrict__ impout)
{
    extern __shared__ char smem_raw[];
    Smem& sm = *reinterpret_cast<Smem*>(smem_raw);

    const int t  = threadIdx.x;
    const int b0 = blockIdx.x * MB;

    // ---- stage resident weights & init state ----
    for (int e = t; e < Hh * Dd; e += NT) sm.histh[e] = __float2half(histW[e]);
    for (int e = t; e < Dd * Dd; e += NT) {
        int k = e >> 6, jj = e & 63;
        sm.frT[e] = frW[jj * Dd + k];
    }
    if (t < Dd) { sm.hist_b[t] = histB[t]; sm.fr_b[t] = frB[t]; }
    for (int e = t; e < MB * Hh; e += NT) sm.cs[e] = 0.f;
    for (int e = t; e < 2 * 2 * Hh; e += NT) sm.hp[e] = 0.f;
    {   // step-0 inputs + alpha[0]  (256 threads, one elem each)
        int r = t >> 6, jj = t & 63;
        int off = ((b0 + r) * Tt + 0) * Dd + jj;
        float xv = values[off], mv = masks[off];
        sm.xs[t] = xv; sm.ms[t] = mv;
        sm.mp[(r >> 1) * 128 + jj * 2 + (r & 1)] = mv;
        int j = t & 63, p = (t >> 6) & 1, par = t >> 7;
        sm.alp[p * 128 + j * 2 + par] = alpha_g[((b0 + 2 * p + par) * Tt + 0) * Dd + j];
    }
    // LSTM bias for this thread's 4 output columns (4t..4t+3)
    u64 bq[4];
    #pragma unroll
    for (int c = 0; c < 4; c++) bq[c] = dup2(lstmB[4 * t + c]);
    __syncthreads();

    float pf_x[2], pf_m[2], pf_a[2];   // prefetch regs (threads 128..255)

    for (int step = 0; step < Tt; ++step) {
        // ---- P1 (all 256): x_h partials, k-split 4-way, into zp alias ----
        float2* cpart = (float2*)sm.zp;
        {
            const int j = t & 63, kq = t >> 6;    // kq 0..3
            u64 a[2] = {0ULL, 0ULL};
            const int k0 = kq * 64;
            #pragma unroll 4
            for (int kk = 0; kk < 64; kk++) {
                int k = k0 + kk;
                u64 wd = dup2(__half2float(sm.histh[k * Dd + j]));
                a[0] = fma2(*(const u64*)(sm.hp + 0 * 512 + k * 2), wd, a[0]);
                a[1] = fma2(*(const u64*)(sm.hp + 1 * 512 + k * 2), wd, a[1]);
            }
            #pragma unroll
            for (int p = 0; p < 2; p++) {
                float a0, a1; upk2(a[p], a0, a1);
                cpart[(kq * 2 + p) * 64 + j] = make_float2(a0, a1);
            }
        }
        __syncthreads();

        // ---- P3: threads 0-127 {reduce->x_c; z_h->c_c->impout} | 128-255 {prefetch}
        if (t < 128) {
            const int j = t & 63, p = t >> 6;     // p 0..1
            const float* cp = (const float*)cpart;
            float xh[2];
            #pragma unroll
            for (int par = 0; par < 2; par++) {
                float s = 0.f;
                #pragma unroll
                for (int kq = 0; kq < 4; kq++)
                    s += cp[((kq * 2 + p) * 64 + j) * 2 + par];
                xh[par] = s + sm.hist_b[j];
                int r = 2 * p + par;
                float m = sm.ms[r * Dd + j], x = sm.xs[r * Dd + j];
                float xc = m * x + (1.f - m) * xh[par];
                sm.xcp[p * 128 + j * 2 + par] = xc;
                sm.xhp[p * 128 + j * 2 + par] = xh[par];
            }
            asm volatile("bar.sync 1, 128;" ::: "memory");
            u64 z = dup2(sm.fr_b[j]);
            #pragma unroll 4
            for (int k = 0; k < Dd; k++)
                z = fma2(*(const u64*)(sm.xcp + p * 128 + k * 2),
                         dup2(sm.frT[k * Dd + j]), z);
            float z0, z1; upk2(z, z0, z1);
            float2 al = *(const float2*)(sm.alp + p * 128 + j * 2);
            int r0 = 2 * p, r1 = r0 + 1;
            float m0 = sm.ms[r0 * Dd + j], m1 = sm.ms[r1 * Dd + j];
            float x0 = sm.xs[r0 * Dd + j], x1 = sm.xs[r1 * Dd + j];
            float ch0 = al.x * z0 + (1.f - al.x) * xh[0];
            float ch1 = al.y * z1 + (1.f - al.y) * xh[1];
            float cc0 = m0 * x0 + (1.f - m0) * ch0;
            float cc1 = m1 * x1 + (1.f - m1) * ch1;
            *(float2*)(sm.ccp + p * 128 + j * 2) = make_float2(cc0, cc1);
            impout[(r0 + b0) * Tt * Dd + step * Dd + j] = cc0;
            impout[(r1 + b0) * Tt * Dd + step * Dd + j] = cc1;
        } else if (step + 1 < Tt) {
            const int u = t - 128;
            #pragma unroll
            for (int s = 0; s < 2; s++) {
                int e = u + s * 128;
                int r = e >> 6, jj = e & 63;
                int off = ((b0 + r) * Tt + (step + 1)) * Dd + jj;
                pf_x[s] = values[off]; pf_m[s] = masks[off];
                int p = (e >> 6) & 1, par = e >> 7;
                pf_a[s] = alpha_g[((b0 + 2 * p + par) * Tt + step + 1) * Dd + jj];
            }
            {
                int r = u >> 5, c0 = (u & 31) * 8;
                const float* gsrc = Gh_g + ((b0 + r) * Tt + (step + 1)) * Hh + c0;
                float4 g0 = *(const float4*)gsrc;
                float4 g1 = *(const float4*)(gsrc + 4);
                *(float4*)(sm.gh + r * Hh + c0)     = g0;
                *(float4*)(sm.gh + r * Hh + c0 + 4) = g1;
            }
        }
        __syncthreads();

        // ---- P4 (all 256): z = b + h@Wrk + cc@Wk_cc + m@Wk_m ;
        //      4 cols x 2 pairs per thread; fp16 uint2 weights; dist-8 ----
        {
            u64 acc[4][2];
            #pragma unroll
            for (int c = 0; c < 4; c++) { acc[c][0] = bq[c]; acc[c][1] = bq[c]; }

            // recurrent part, rows 0..255 of WEHrk (uint2 row stride 256)
            const uint2* rk = (const uint2*)WEHrk_g + t;   // this thread's 2 u32
            uint2 a0 = rk[0],        a1 = rk[256];
            uint2 a2 = rk[2 * 256],  a3 = rk[3 * 256];
            uint2 c0 = rk[4 * 256],  c1 = rk[5 * 256];
            uint2 c2 = rk[6 * 256],  c3 = rk[7 * 256];
            #pragma unroll 2
            for (int k = 0; k < Hh; k += 8) {
                int kn = (k + 8) & 255;
                uint2 na0 = rk[kn * 256],       na1 = rk[(kn + 1) * 256];
                uint2 na2 = rk[(kn + 2) * 256], na3 = rk[(kn + 3) * 256];
                eblk2<512>(sm.hp, k,     a0, a1, acc);
                eblk2<512>(sm.hp, k + 2, a2, a3, acc);
                int km = (k + 12) & 255;
                uint2 nc0 = rk[km * 256],       nc1 = rk[(km + 1) * 256];
                uint2 nc2 = rk[(km + 2) * 256], nc3 = rk[(km + 3) * 256];
                eblk2<512>(sm.hp, k + 4, c0, c1, acc);
                eblk2<512>(sm.hp, k + 6, c2, c3, acc);
                a0 = na0; a1 = na1; a2 = na2; a3 = na3;
                c0 = nc0; c1 = nc1; c2 = nc2; c3 = nc3;
            }

            // c_c part, rows 0..63 of WEHk
            const uint2* kk = (const uint2*)WEHk_g + t;
            a0 = kk[0];       a1 = kk[256];
            a2 = kk[2 * 256]; a3 = kk[3 * 256];
            c0 = kk[4 * 256]; c1 = kk[5 * 256];
            c2 = kk[6 * 256]; c3 = kk[7 * 256];
            #pragma unroll 2
            for (int k = 0; k < Dd; k += 8) {
                int kn = (k + 8) & 63;
                uint2 na0 = kk[kn * 256],       na1 = kk[(kn + 1) * 256];
                uint2 na2 = kk[(kn + 2) * 256], na3 = kk[(kn + 3) * 256];
                eblk2<128>(sm.ccp, k,     a0, a1, acc);
                eblk2<128>(sm.ccp, k + 2, a2, a3, acc);
                int km = (k + 12) & 63;
                uint2 nc0 = kk[km * 256],       nc1 = kk[(km + 1) * 256];
                uint2 nc2 = kk[(km + 2) * 256], nc3 = kk[(km + 3) * 256];
                eblk2<128>(sm.ccp, k + 4, c0, c1, acc);
                eblk2<128>(sm.ccp, k + 6, c2, c3, acc);
                a0 = na0; a1 = na1; a2 = na2; a3 = na3;
                c0 = nc0; c1 = nc1; c2 = nc2; c3 = nc3;
            }

            // m part, rows 64..127 of WEHk
            const uint2* km2 = kk + 64 * 256;
            a0 = km2[0];       a1 = km2[256];
            a2 = km2[2 * 256]; a3 = km2[3 * 256];
            c0 = km2[4 * 256]; c1 = km2[5 * 256];
            c2 = km2[6 * 256]; c3 = km2[7 * 256];
            #pragma unroll 2
            for (int k = 0; k < Dd; k += 8) {
                int kn = (k + 8) & 63;
                uint2 na0 = km2[kn * 256],       na1 = km2[(kn + 1) * 256];
                uint2 na2 = km2[(kn + 2) * 256], na3 = km2[(kn + 3) * 256];
                eblk2<128>(sm.mp, k,     a0, a1, acc);
                eblk2<128>(sm.mp, k + 2, a2, a3, acc);
                int km_ = (k + 12) & 63;
                uint2 nc0 = km2[km_ * 256],       nc1 = km2[(km_ + 1) * 256];
                uint2 nc2 = km2[(km_ + 2) * 256], nc3 = km2[(km_ + 3) * 256];
                eblk2<128>(sm.mp, k + 4, c0, c1, acc);
                eblk2<128>(sm.mp, k + 6, c2, c3, acc);
                a0 = na0; a1 = na1; a2 = na2; a3 = na3;
                c0 = nc0; c1 = nc1; c2 = nc2; c3 = nc3;
            }

            // epilogue: activations -> zp  (cols 4t..4t+3, both pairs)
            const int gate = t >> 6;
            #pragma unroll
            for (int p = 0; p < 2; p++) {
                float r8[8];
                #pragma unroll
                for (int c = 0; c < 4; c++) {
                    float v0, v1; upk2(acc[c][p], v0, v1);
                    if (gate == 2) { r8[2 * c] = tanhfast(v0); r8[2 * c + 1] = tanhfast(v1); }
                    else           { r8[2 * c] = sigf(v0);     r8[2 * c + 1] = sigf(v1);     }
                }
                *(float4*)(sm.zp + p * 2048 + 8 * t)     = make_float4(r8[0], r8[1], r8[2], r8[3]);
                *(float4*)(sm.zp + p * 2048 + 8 * t + 4) = make_float4(r8[4], r8[5], r8[6], r8[7]);
            }
        }
        __syncthreads();

        // ---- P5: threads 0-127 {c,h update + fused decay} | 128-255 {commit} --
        if (t < 128) {
            int r = t >> 5;                 // 0..3
            int p = r >> 1, par = r & 1;
            int cb = (t & 31) * 8;
            bool last = (step == Tt - 1);
            float4 gA = *(const float4*)(sm.gh + r * Hh + cb);
            float4 gB = *(const float4*)(sm.gh + r * Hh + cb + 4);
            float gv8[8] = {gA.x, gA.y, gA.z, gA.w, gB.x, gB.y, gB.z, gB.w};
            #pragma unroll
            for (int cc = 0; cc < 8; cc++) {
                int c = cb + cc;
                float iv = sm.zp[p * 2048 + (0 * Hh + c) * 2 + par];
                float fv = sm.zp[p * 2048 + (1 * Hh + c) * 2 + par];
                float gg = sm.zp[p * 2048 + (2 * Hh + c) * 2 + par];
                float ov = sm.zp[p * 2048 + (3 * Hh + c) * 2 + par];
                float cold = sm.cs[r * Hh + c];
                float cnew = fv * cold + iv * gg;
                sm.cs[r * Hh + c] = cnew;
                float hh = ov * tanhfast(cnew);
                if (!last) hh *= gv8[cc];
                sm.hp[p * 512 + c * 2 + par] = hh;
            }
        } else if (step + 1 < Tt) {
            const int u = t - 128;
            #pragma unroll
            for (int s = 0; s < 2; s++) {
                int e = u + s * 128;
                int r = e >> 6, jj = e & 63;
                sm.xs[e] = pf_x[s]; sm.ms[e] = pf_m[s];
                sm.mp[(r >> 1) * 128 + jj * 2 + (r & 1)] = pf_m[s];
                int p = (e >> 6) & 1, par = e >> 7;
                sm.alp[p * 128 + jj * 2 + par] = pf_a[s];
            }
        }
        __syncthreads();
    }

    // ---- final: y = h @ out_W + out_b ----
    {
        int w = t >> 5, lane = t & 31;
        if (w < MB) {
            float s = 0.f;
            for (int k = lane; k < Hh; k += 32)
                s += sm.hp[(w >> 1) * 512 + k * 2 + (w & 1)] * outW[k];
            #pragma unroll
            for (int o = 16; o > 0; o >>= 1)
                s += __shfl_down_sync(0xffffffffu, s, o);
            if (lane == 0) yout[b0 + w] = s + outB[0];
        }
    }
}

// ================================ launcher ================================

extern "C" void kernel_launch(void* const* d_in, const int* in_sizes, int n_in,
                              void* d_out, int out_size) {
    const float* values = (const float*)d_in[0];
    const float* masks  = (const float*)d_in[1];
    const float* deltas = (const float*)d_in[2];
    const float* tdhW   = (const float*)d_in[3];
    const float* tdhB   = (const float*)d_in[4];
    const float* tdxW   = (const float*)d_in[5];
    const float* tdxB   = (const float*)d_in[6];
    const float* histW  = (const float*)d_in[7];
    const float* histB  = (const float*)d_in[8];
    const float* frW    = (const float*)d_in[9];
    const float* frB    = (const float*)d_in[10];
    const float* wcW    = (const float*)d_in[11];
    const float* wcB    = (const float*)d_in[12];
    const float* lstmK  = (const float*)d_in[13];
    const float* lstmRK = (const float*)d_in[14];
    const float* lstmB  = (const float*)d_in[15];
    const float* outW   = (const float*)d_in[16];
    const float* outB   = (const float*)d_in[17];

    float* yout   = (float*)d_out;       // y_h [B,1] first
    float* impout = yout + Bsz;          // imputations [B,T,D]

    transpose_kernel<<<(Hh * Dd + Dd * Dd + 255) / 256, 256>>>(tdhW, tdxW);
    pack_h_kernel<<<(384 * 1024 + 255) / 256, 256>>>(lstmRK, lstmK);
    pre_ga_kernel<<<Bsz * Tt / 8, 256>>>(deltas, masks, tdhB, tdxB, wcW, wcB);

    cudaFuncSetAttribute(rits_kernel, cudaFuncAttributeMaxDynamicSharedMemorySize,
                         (int)sizeof(Smem));
    rits_kernel<<<GRID, NT, sizeof(Smem)>>>(
        values, masks, histW, histB, frW, frB,
        lstmB, outW, outB, yout, impout);
}